// round 13
// baseline (speedup 1.0000x reference)
#include <cuda_runtime.h>
#include <cuda_fp16.h>

// Problem geometry
#define DW   128
#define PL   (128*128)
#define V    (128*128*128)
#define NBC  8
#define NTOT (NBC*V)
#define NB_SPATIAL (2*V)
#define NTILES (NBC*32*32)        // flags: bc x dtg(32) x ht(32); tile = 128w x 4h x 4d
#define SLOT4(p) (((p) + 8) & 3)  // ring-of-4 slot, valid for p >= -8
#define NBLK 512                  // erode grid size (all co-resident: 4/SM x 148+ SMs)

// Static device scratch (allowed). op fields stored as fp16 (values in [0,1]).
__device__ __half        g_bufA[NTOT];
__device__ __half        g_bufB[NTOT];
__device__ unsigned char g_flagA[NTILES];
__device__ unsigned char g_flagB[NTILES];
__device__ double        g_acc;     // zero-init; reset by finalizer
__device__ unsigned int  g_cnt;     // zero-init; reset by finalizer
__device__ unsigned int  g_bar;     // zero-init; reset by finalizer

// ---- fp16 <-> fp32 quad helpers -------------------------------------------
__device__ __forceinline__ uint2 f4_to_h4(float4 v)
{
    __half2 lo = __float22half2_rn(make_float2(v.x, v.y));
    __half2 hi = __float22half2_rn(make_float2(v.z, v.w));
    uint2 r;
    r.x = *(unsigned int*)&lo;
    r.y = *(unsigned int*)&hi;
    return r;
}
__device__ __forceinline__ float4 h4_to_f4(unsigned int a, unsigned int b)
{
    float2 lo = __half22float2(*(__half2*)&a);
    float2 hi = __half22float2(*(__half2*)&b);
    return make_float4(lo.x, lo.y, hi.x, hi.y);
}

// ---------------------------------------------------------------------------
// Kernel 1: softmax over C + squared one-hot error -> bufA (op0, fp16).
// Streaming (__ldcs) input reads; also resets g_acc-adjacent state and marks
// all bufA tiles active.
// ---------------------------------------------------------------------------
__global__ void init_op_kernel(const float* __restrict__ inp,
                               const int*   __restrict__ tgt,
                               __half*      __restrict__ dst)
{
    int q = blockIdx.x * blockDim.x + threadIdx.x;      // quad index
    if (q == 0) g_acc = 0.0;
    if (q < NTILES) g_flagA[q] = 1;
    if (q >= NB_SPATIAL / 4) return;

    int idx = q * 4;
    int b = idx >> 21;
    int s = idx & (V - 1);

    const float* ip = inp + (size_t)b * 4 * V + s;
    float4 x0 = __ldcs((const float4*)(ip));
    float4 x1 = __ldcs((const float4*)(ip + V));
    float4 x2 = __ldcs((const float4*)(ip + 2 * V));
    float4 x3 = __ldcs((const float4*)(ip + 3 * V));
    int4   t4 = __ldcs((const int4*)(tgt + idx));

    float4 o0, o1, o2, o3;
    #pragma unroll
    for (int j = 0; j < 4; ++j) {
        float a0 = ((const float*)&x0)[j];
        float a1 = ((const float*)&x1)[j];
        float a2 = ((const float*)&x2)[j];
        float a3 = ((const float*)&x3)[j];
        int   t  = ((const int*)&t4)[j];

        float e0 = __expf(a0);
        float e1 = __expf(a1);
        float e2 = __expf(a2);
        float e3 = __expf(a3);
        float inv = 1.0f / (e0 + e1 + e2 + e3);

        float p0 = e0 * inv - (t == 0 ? 1.0f : 0.0f);
        float p1 = e1 * inv - (t == 1 ? 1.0f : 0.0f);
        float p2 = e2 * inv - (t == 2 ? 1.0f : 0.0f);
        float p3 = e3 * inv - (t == 3 ? 1.0f : 0.0f);

        ((float*)&o0)[j] = p0 * p0;
        ((float*)&o1)[j] = p1 * p1;
        ((float*)&o2)[j] = p2 * p2;
        ((float*)&o3)[j] = p3 * p3;
    }

    __half* op = dst + (size_t)b * 4 * V + s;
    *(uint2*)(op)         = f4_to_h4(o0);
    *(uint2*)(op + V)     = f4_to_h4(o1);
    *(uint2*)(op + 2 * V) = f4_to_h4(o2);
    *(uint2*)(op + 3 * V) = f4_to_h4(o3);
}

// ---------------------------------------------------------------------------
// Fused-pair erosion helpers (ring-of-4 fp32 smem buffers, fp16 global).
// All global field reads use __ldcg (L2-only): the persistent kernel gets no
// per-launch L1 flush, and L1 is not coherent across SMs.
// ---------------------------------------------------------------------------
__device__ __forceinline__ void load_src_plane(
    float (*ssrc)[12][128], const __half* __restrict__ src,
    size_t base_c, int p, int h0, int tid)
{
    const int slot = SLOT4(p);
    if (tid < 192) {
        int r = tid >> 4, cu = tid & 15;
        int h = h0 - 2 + r;
        float4 a = make_float4(0.f, 0.f, 0.f, 0.f);
        float4 b = a;
        if ((unsigned)p < 128u && (unsigned)h < 128u) {
            uint4 u = __ldcg((const uint4*)(src + base_c + (size_t)p * PL +
                                            (size_t)h * DW + cu * 8));
            a = h4_to_f4(u.x, u.y);
            b = h4_to_f4(u.z, u.w);
        }
        *(float4*)&ssrc[slot][r][cu * 8]     = a;
        *(float4*)&ssrc[slot][r][cu * 8 + 4] = b;
    }
}

__device__ __forceinline__ float mid_row(
    float (*ssrc)[12][128], float (*smid)[10][128],
    int m, int rr, int h0, int tx, float kw, float bi, int dlo, int dhi)
{
    const int w0 = tx * 4;
    const int h  = h0 - 1 + rr;
    float4 v = make_float4(0.f, 0.f, 0.f, 0.f);
    if ((unsigned)m < 128u && (unsigned)h < 128u) {
        const int r  = rr + 1;                  // src row for this h
        const int s0 = SLOT4(m);
        float4 c  = *(float4*)&ssrc[s0][r][w0];
        float4 up = *(float4*)&ssrc[s0][r - 1][w0];
        float4 dn = *(float4*)&ssrc[s0][r + 1][w0];
        float4 fm = *(float4*)&ssrc[SLOT4(m - 1)][r][w0];
        float4 fp = *(float4*)&ssrc[SLOT4(m + 1)][r][w0];
        float lf = (tx == 0)  ? 0.f : ssrc[s0][r][w0 - 1];
        float rt = (tx == 31) ? 0.f : ssrc[s0][r][w0 + 4];
        v.x = fmaxf(fmaf(c.x + lf  + c.y + up.x + dn.x + fm.x + fp.x, kw, bi), 0.f);
        v.y = fmaxf(fmaf(c.y + c.x + c.z + up.y + dn.y + fm.y + fp.y, kw, bi), 0.f);
        v.z = fmaxf(fmaf(c.z + c.y + c.w + up.z + dn.z + fm.z + fp.z, kw, bi), 0.f);
        v.w = fmaxf(fmaf(c.w + c.z + rt  + up.w + dn.w + fm.w + fp.w, kw, bi), 0.f);
    }
    *(float4*)&smid[SLOT4(m)][rr][w0] = v;
    if (m >= dlo && m <= dhi && rr >= 1 && rr <= 8)
        return (v.x + v.y) + (v.z + v.w);
    return 0.f;
}

__device__ __forceinline__ float out_plane(
    float (*smid)[10][128], __half* __restrict__ dst, size_t base_c,
    int dd, int h0, int tx, int ty, float kw, float bi, int store)
{
    const int w0 = tx * 4;
    const int rr = ty + 1;
    const int s0 = SLOT4(dd);
    float4 c  = *(float4*)&smid[s0][rr][w0];
    float4 up = *(float4*)&smid[s0][rr - 1][w0];
    float4 dn = *(float4*)&smid[s0][rr + 1][w0];
    float4 fm = *(float4*)&smid[SLOT4(dd - 1)][rr][w0];
    float4 fp = *(float4*)&smid[SLOT4(dd + 1)][rr][w0];
    float lf = (tx == 0)  ? 0.f : smid[s0][rr][w0 - 1];
    float rt = (tx == 31) ? 0.f : smid[s0][rr][w0 + 4];
    float4 v;
    v.x = fmaxf(fmaf(c.x + lf  + c.y + up.x + dn.x + fm.x + fp.x, kw, bi), 0.f);
    v.y = fmaxf(fmaf(c.y + c.x + c.z + up.y + dn.y + fm.y + fp.y, kw, bi), 0.f);
    v.z = fmaxf(fmaf(c.z + c.y + c.w + up.z + dn.z + fm.z + fp.z, kw, bi), 0.f);
    v.w = fmaxf(fmaf(c.w + c.z + rt  + up.w + dn.w + fm.w + fp.w, kw, bi), 0.f);
    if (store)
        *(uint2*)(dst + base_c + (size_t)dd * PL + (size_t)(h0 + ty) * DW + w0) =
            f4_to_h4(v);
    return (v.x + v.y) + (v.z + v.w);
}

// ---------------------------------------------------------------------------
// Software grid barrier. Valid because all NBLK blocks are co-resident
// (512 blocks at 4/SM on >=128 SMs). Monotonic counter; targets NBLK*(p+1).
// ---------------------------------------------------------------------------
__device__ __forceinline__ void grid_barrier(int tid, unsigned target)
{
    __syncthreads();
    if (tid == 0) {
        __threadfence();
        atomicAdd(&g_bar, 1u);
        while (*(volatile unsigned int*)&g_bar < target)
            __nanosleep(64);
        __threadfence();
    }
    __syncthreads();
}

// ---------------------------------------------------------------------------
// Kernel 2 (x1, persistent): ALL 5 fused erosion pairs (10 steps) with grid
// barriers between phases. Each phase: TWO erosion steps, 2 d-planes per
// barrier period, tile sparsity with whole-block skip. Finalizes the mean via
// a completion counter.
// block (32,8)=256 thr; grid (1, 16 hb, 4 db * 8 bc) = 512 blocks; 1 wave.
// ---------------------------------------------------------------------------
__global__ void __launch_bounds__(256, 4)
erode_persist_kernel(const float* __restrict__ weight,
                     const float* __restrict__ kern,
                     const float* __restrict__ bias,
                     float* __restrict__ outp)
{
    const int tx  = threadIdx.x;
    const int ty  = threadIdx.y;
    const int tid = ty * 32 + tx;
    const int hb  = blockIdx.y;          // 0..15
    const int db  = blockIdx.z & 3;      // 0..3
    const int bc  = blockIdx.z >> 2;     // 0..7

    const int h0   = hb * 8;
    const int d0   = db * 32;
    const int ht0  = hb * 2;
    const int dtg0 = d0 >> 2;
    const size_t base_c = (size_t)bc * V;

    const float kw  = __ldg(&kern[13]);
    const float bi  = __ldg(&bias[bc & 3]);
    const float wgt = __ldg(&weight[bc]);

    __shared__ unsigned char s_f[4][10];     // src flags: ht0-1..+2  x  dtg0-1..+8
    __shared__ unsigned char s_act[8];       // per-segment activity
    __shared__ unsigned char s_dstf[8][2];   // dst flags per segment / ht tile
    __shared__ unsigned char s_skip;
    __shared__ __align__(16) float s_src[4][12][128];
    __shared__ __align__(16) float s_mid[4][10][128];
    __shared__ float s_w[8];

    #pragma unroll 1
    for (int p = 0; p < 5; ++p) {
        const __half* src = (p & 1) ? g_bufB : g_bufA;
        __half*       dst = (p & 1) ? g_bufA : g_bufB;
        const unsigned char* srcFlag = (p & 1) ? g_flagB : g_flagA;
        unsigned char*       dstFlag = (p & 1) ? g_flagA : g_flagB;
        const float c1 = (float)((2 * p + 1) * (2 * p + 1));
        const float c2 = (float)((2 * p + 2) * (2 * p + 2));
        const int store = (p < 4) ? 1 : 0;

        // --- cooperative flag gather (one pass per phase) ---
        if (tid < 40) {
            int fh = tid & 3, fg = tid >> 2;     // 4 x 10
            int ht = ht0 - 1 + fh;
            int g  = dtg0 - 1 + fg;
            unsigned char v = 0;
            if ((unsigned)ht < 32u && (unsigned)g < 32u)
                v = __ldcg(&srcFlag[bc * 1024 + g * 32 + ht]);
            s_f[fh][fg] = v;
        }
        if (tid >= 64 && tid < 80) {
            int k = tid - 64, sg = k >> 1, hh = k & 1;
            s_dstf[sg][hh] = store ? __ldcg(&dstFlag[bc * 1024 + (dtg0 + sg) * 32 + ht0 + hh]) : 0;
        }
        __syncthreads();
        if (tid < 8) {
            unsigned a = 0;
            #pragma unroll
            for (int dh = 0; dh < 4; ++dh)
                #pragma unroll
                for (int dg = 0; dg < 3; ++dg)
                    a |= s_f[dh][tid + dg];
            s_act[tid] = a ? 1 : 0;
        }
        __syncthreads();
        if (tid == 0) {
            unsigned any = 0;
            #pragma unroll
            for (int s = 0; s < 8; ++s)
                any |= (unsigned)s_act[s] | s_dstf[s][0] | s_dstf[s][1];
            s_skip = any ? 0 : 1;
        }
        __syncthreads();

        if (!s_skip) {
            float acc_mid   = 0.f;   // per-thread, whole block
            float block_out = 0.f;   // only meaningful in thread 0
            bool  have = false;

            #pragma unroll 1
            for (int seg = 0; seg < 8; ++seg) {
                const int ds  = d0 + seg * 4;
                const int dtg = dtg0 + seg;

                if (!s_act[seg]) {
                    // dead neighborhood -> output tile must be zero
                    if (store && s_dstf[seg][ty >> 2]) {
                        uint2 z; z.x = 0u; z.y = 0u;
                        #pragma unroll
                        for (int j = 0; j < 4; ++j)
                            *(uint2*)(dst + base_c + (size_t)(ds + j) * PL +
                                      (size_t)(h0 + ty) * DW + tx * 4) = z;
                        if (tx == 0 && (ty & 3) == 0)
                            dstFlag[bc * 1024 + dtg * 32 + ht0 + (ty >> 2)] = 0;
                    }
                    have = false;
                    continue;
                }

                if (!have) {
                    // prologue: fill src ring (4 planes), then mids ds-1, ds
                    load_src_plane(s_src, src, base_c, ds - 2, h0, tid);
                    load_src_plane(s_src, src, base_c, ds - 1, h0, tid);
                    load_src_plane(s_src, src, base_c, ds,     h0, tid);
                    load_src_plane(s_src, src, base_c, ds + 1, h0, tid);
                    __syncthreads();
                    acc_mid += mid_row(s_src, s_mid, ds - 1, ty, h0, tx, kw, bi, d0, d0 + 31);
                    if (ty < 2)
                        acc_mid += mid_row(s_src, s_mid, ds - 1, ty + 8, h0, tx, kw, bi, d0, d0 + 31);
                    acc_mid += mid_row(s_src, s_mid, ds, ty, h0, tx, kw, bi, d0, d0 + 31);
                    if (ty < 2)
                        acc_mid += mid_row(s_src, s_mid, ds, ty + 8, h0, tx, kw, bi, d0, d0 + 31);
                    __syncthreads();
                    have = true;
                }

                float segsum = 0.f;
                #pragma unroll
                for (int j = 0; j < 4; j += 2) {
                    const int dd = ds + j;
                    load_src_plane(s_src, src, base_c, dd + 2, h0, tid);
                    load_src_plane(s_src, src, base_c, dd + 3, h0, tid);
                    __syncthreads();
                    acc_mid += mid_row(s_src, s_mid, dd + 1, ty, h0, tx, kw, bi, d0, d0 + 31);
                    if (ty < 2)
                        acc_mid += mid_row(s_src, s_mid, dd + 1, ty + 8, h0, tx, kw, bi, d0, d0 + 31);
                    acc_mid += mid_row(s_src, s_mid, dd + 2, ty, h0, tx, kw, bi, d0, d0 + 31);
                    if (ty < 2)
                        acc_mid += mid_row(s_src, s_mid, dd + 2, ty + 8, h0, tx, kw, bi, d0, d0 + 31);
                    __syncthreads();
                    segsum += out_plane(s_mid, dst, base_c, dd,     h0, tx, ty, kw, bi, store);
                    segsum += out_plane(s_mid, dst, base_c, dd + 1, h0, tx, ty, kw, bi, store);
                }

                // per-segment reduction -> flags + running out-sum
                float r = segsum;
                #pragma unroll
                for (int off = 16; off > 0; off >>= 1)
                    r += __shfl_down_sync(0xffffffffu, r, off);
                if (tx == 0) s_w[ty] = r;
                __syncthreads();
                if (tid == 0) {
                    float t0 = (s_w[0] + s_w[1]) + (s_w[2] + s_w[3]);
                    float t1 = (s_w[4] + s_w[5]) + (s_w[6] + s_w[7]);
                    if (store) {
                        dstFlag[bc * 1024 + dtg * 32 + ht0]     = (t0 > 0.f) ? 1 : 0;
                        dstFlag[bc * 1024 + dtg * 32 + ht0 + 1] = (t1 > 0.f) ? 1 : 0;
                    }
                    block_out += t0 + t1;
                }
                __syncthreads();
            }

            // block reduction of mid-sum + single atomic for this phase
            float r = acc_mid;
            #pragma unroll
            for (int off = 16; off > 0; off >>= 1)
                r += __shfl_down_sync(0xffffffffu, r, off);
            if (tx == 0) s_w[ty] = r;
            __syncthreads();
            if (tid == 0) {
                float midsum = ((s_w[0] + s_w[1]) + (s_w[2] + s_w[3])) +
                               ((s_w[4] + s_w[5]) + (s_w[6] + s_w[7]));
                double total = (double)c1 * (double)midsum + (double)c2 * (double)block_out;
                if (total != 0.0)
                    atomicAdd(&g_acc, total * (double)wgt);
            }
        }

        if (p < 4)
            grid_barrier(tid, (unsigned)(NBLK * (p + 1)));
    }

    // ---- finalize: last finished block writes the mean and resets state ----
    if (tid == 0) {
        __threadfence();
        unsigned old = atomicAdd(&g_cnt, 1u);
        if (old == NBLK - 1) {
            volatile double* pacc = &g_acc;
            double acc = *pacc;
            outp[0] = (float)(acc / (double)NTOT);
            *pacc = 0.0;                       // restore invariants for next replay
            *(volatile unsigned int*)&g_bar = 0u;
            __threadfence();
            g_cnt = 0;
        }
    }
}

// ---------------------------------------------------------------------------
extern "C" void kernel_launch(void* const* d_in, const int* in_sizes, int n_in,
                              void* d_out, int out_size)
{
    const float* inp    = (const float*)d_in[0];
    const int*   tgt    = (const int*)  d_in[1];
    const float* weight = (const float*)d_in[2];
    const float* kern   = (const float*)d_in[3];
    const float* bias   = (const float*)d_in[4];
    float* out = (float*)d_out;

    __half* bufA; cudaGetSymbolAddress((void**)&bufA, g_bufA);

    init_op_kernel<<<(NB_SPATIAL / 4 + 255) / 256, 256>>>(inp, tgt, bufA);

    dim3 blk(32, 8, 1);
    dim3 grd(1, 16, 4 * NBC);
    erode_persist_kernel<<<grd, blk>>>(weight, kern, bias, out);
}

// round 15
// speedup vs baseline: 1.0033x; 1.0033x over previous
#include <cuda_runtime.h>
#include <cuda_fp16.h>

// Problem geometry
#define DW   128
#define PL   (128*128)
#define V    (128*128*128)
#define NBC  8
#define NTOT (NBC*V)
#define NB_SPATIAL (2*V)
#define NTILES (NBC*32*32)        // flags: bc x dtg(32) x ht(32); tile = 128w x 4h x 4d
#define SLOT4(p) (((p) + 8) & 3)  // ring-of-4 slot, valid for p >= -8
#define NBLK 512                  // erode grid size (all co-resident: 4/SM)

// Static device scratch (allowed). op fields stored as fp16 (values in [0,1]).
__device__ __half        g_bufA[NTOT];
__device__ __half        g_bufB[NTOT];
__device__ unsigned char g_flagA[NTILES];
__device__ unsigned char g_flagB[NTILES];
__device__ double        g_acc;     // zero-init; reset by finalizer
__device__ unsigned int  g_cnt;     // zero-init; reset by finalizer
__device__ unsigned int  g_bar;     // zero-init; reset by finalizer

// ---- fp16 <-> fp32 quad helpers -------------------------------------------
__device__ __forceinline__ uint2 f4_to_h4(float4 v)
{
    __half2 lo = __float22half2_rn(make_float2(v.x, v.y));
    __half2 hi = __float22half2_rn(make_float2(v.z, v.w));
    uint2 r;
    r.x = *(unsigned int*)&lo;
    r.y = *(unsigned int*)&hi;
    return r;
}
__device__ __forceinline__ float4 h4_to_f4(unsigned int a, unsigned int b)
{
    float2 lo = __half22float2(*(__half2*)&a);
    float2 hi = __half22float2(*(__half2*)&b);
    return make_float4(lo.x, lo.y, hi.x, hi.y);
}

// ---------------------------------------------------------------------------
// Kernel 1: softmax over C + squared one-hot error -> bufA (op0, fp16).
// ---------------------------------------------------------------------------
__global__ void init_op_kernel(const float* __restrict__ inp,
                               const int*   __restrict__ tgt,
                               __half*      __restrict__ dst)
{
    int q = blockIdx.x * blockDim.x + threadIdx.x;      // quad index
    if (q == 0) g_acc = 0.0;
    if (q < NTILES) g_flagA[q] = 1;
    if (q >= NB_SPATIAL / 4) return;

    int idx = q * 4;
    int b = idx >> 21;
    int s = idx & (V - 1);

    const float* ip = inp + (size_t)b * 4 * V + s;
    float4 x0 = __ldcs((const float4*)(ip));
    float4 x1 = __ldcs((const float4*)(ip + V));
    float4 x2 = __ldcs((const float4*)(ip + 2 * V));
    float4 x3 = __ldcs((const float4*)(ip + 3 * V));
    int4   t4 = __ldcs((const int4*)(tgt + idx));

    float4 o0, o1, o2, o3;
    #pragma unroll
    for (int j = 0; j < 4; ++j) {
        float a0 = ((const float*)&x0)[j];
        float a1 = ((const float*)&x1)[j];
        float a2 = ((const float*)&x2)[j];
        float a3 = ((const float*)&x3)[j];
        int   t  = ((const int*)&t4)[j];

        float e0 = __expf(a0);
        float e1 = __expf(a1);
        float e2 = __expf(a2);
        float e3 = __expf(a3);
        float inv = 1.0f / (e0 + e1 + e2 + e3);

        float p0 = e0 * inv - (t == 0 ? 1.0f : 0.0f);
        float p1 = e1 * inv - (t == 1 ? 1.0f : 0.0f);
        float p2 = e2 * inv - (t == 2 ? 1.0f : 0.0f);
        float p3 = e3 * inv - (t == 3 ? 1.0f : 0.0f);

        ((float*)&o0)[j] = p0 * p0;
        ((float*)&o1)[j] = p1 * p1;
        ((float*)&o2)[j] = p2 * p2;
        ((float*)&o3)[j] = p3 * p3;
    }

    __half* op = dst + (size_t)b * 4 * V + s;
    *(uint2*)(op)         = f4_to_h4(o0);
    *(uint2*)(op + V)     = f4_to_h4(o1);
    *(uint2*)(op + 2 * V) = f4_to_h4(o2);
    *(uint2*)(op + 3 * V) = f4_to_h4(o3);
}

// ---------------------------------------------------------------------------
// Plane loaders: default-cached (fresh-launch kernels) and L2-only (persistent
// tail, where L1 may hold stale lines from an earlier phase).
// ---------------------------------------------------------------------------
__device__ __forceinline__ void load_src_plane(
    float (*ssrc)[12][128], const __half* __restrict__ src,
    size_t base_c, int p, int h0, int tid)
{
    const int slot = SLOT4(p);
    if (tid < 192) {
        int r = tid >> 4, cu = tid & 15;
        int h = h0 - 2 + r;
        float4 a = make_float4(0.f, 0.f, 0.f, 0.f);
        float4 b = a;
        if ((unsigned)p < 128u && (unsigned)h < 128u) {
            uint4 u = *(const uint4*)(src + base_c + (size_t)p * PL +
                                      (size_t)h * DW + cu * 8);
            a = h4_to_f4(u.x, u.y);
            b = h4_to_f4(u.z, u.w);
        }
        *(float4*)&ssrc[slot][r][cu * 8]     = a;
        *(float4*)&ssrc[slot][r][cu * 8 + 4] = b;
    }
}

__device__ __forceinline__ void load_src_plane_cg(
    float (*ssrc)[12][128], const __half* __restrict__ src,
    size_t base_c, int p, int h0, int tid)
{
    const int slot = SLOT4(p);
    if (tid < 192) {
        int r = tid >> 4, cu = tid & 15;
        int h = h0 - 2 + r;
        float4 a = make_float4(0.f, 0.f, 0.f, 0.f);
        float4 b = a;
        if ((unsigned)p < 128u && (unsigned)h < 128u) {
            uint4 u = __ldcg((const uint4*)(src + base_c + (size_t)p * PL +
                                            (size_t)h * DW + cu * 8));
            a = h4_to_f4(u.x, u.y);
            b = h4_to_f4(u.z, u.w);
        }
        *(float4*)&ssrc[slot][r][cu * 8]     = a;
        *(float4*)&ssrc[slot][r][cu * 8 + 4] = b;
    }
}

// ---------------------------------------------------------------------------
// Stencil helpers
// ---------------------------------------------------------------------------
__device__ __forceinline__ float mid_row(
    float (*ssrc)[12][128], float (*smid)[10][128],
    int m, int rr, int h0, int tx, float kw, float bi, int dlo, int dhi)
{
    const int w0 = tx * 4;
    const int h  = h0 - 1 + rr;
    float4 v = make_float4(0.f, 0.f, 0.f, 0.f);
    if ((unsigned)m < 128u && (unsigned)h < 128u) {
        const int r  = rr + 1;                  // src row for this h
        const int s0 = SLOT4(m);
        float4 c  = *(float4*)&ssrc[s0][r][w0];
        float4 up = *(float4*)&ssrc[s0][r - 1][w0];
        float4 dn = *(float4*)&ssrc[s0][r + 1][w0];
        float4 fm = *(float4*)&ssrc[SLOT4(m - 1)][r][w0];
        float4 fp = *(float4*)&ssrc[SLOT4(m + 1)][r][w0];
        float lf = (tx == 0)  ? 0.f : ssrc[s0][r][w0 - 1];
        float rt = (tx == 31) ? 0.f : ssrc[s0][r][w0 + 4];
        v.x = fmaxf(fmaf(c.x + lf  + c.y + up.x + dn.x + fm.x + fp.x, kw, bi), 0.f);
        v.y = fmaxf(fmaf(c.y + c.x + c.z + up.y + dn.y + fm.y + fp.y, kw, bi), 0.f);
        v.z = fmaxf(fmaf(c.z + c.y + c.w + up.z + dn.z + fm.z + fp.z, kw, bi), 0.f);
        v.w = fmaxf(fmaf(c.w + c.z + rt  + up.w + dn.w + fm.w + fp.w, kw, bi), 0.f);
    }
    *(float4*)&smid[SLOT4(m)][rr][w0] = v;
    if (m >= dlo && m <= dhi && rr >= 1 && rr <= 8)
        return (v.x + v.y) + (v.z + v.w);
    return 0.f;
}

__device__ __forceinline__ float out_plane(
    float (*smid)[10][128], __half* __restrict__ dst, size_t base_c,
    int dd, int h0, int tx, int ty, float kw, float bi, int store)
{
    const int w0 = tx * 4;
    const int rr = ty + 1;
    const int s0 = SLOT4(dd);
    float4 c  = *(float4*)&smid[s0][rr][w0];
    float4 up = *(float4*)&smid[s0][rr - 1][w0];
    float4 dn = *(float4*)&smid[s0][rr + 1][w0];
    float4 fm = *(float4*)&smid[SLOT4(dd - 1)][rr][w0];
    float4 fp = *(float4*)&smid[SLOT4(dd + 1)][rr][w0];
    float lf = (tx == 0)  ? 0.f : smid[s0][rr][w0 - 1];
    float rt = (tx == 31) ? 0.f : smid[s0][rr][w0 + 4];
    float4 v;
    v.x = fmaxf(fmaf(c.x + lf  + c.y + up.x + dn.x + fm.x + fp.x, kw, bi), 0.f);
    v.y = fmaxf(fmaf(c.y + c.x + c.z + up.y + dn.y + fm.y + fp.y, kw, bi), 0.f);
    v.z = fmaxf(fmaf(c.z + c.y + c.w + up.z + dn.z + fm.z + fp.z, kw, bi), 0.f);
    v.w = fmaxf(fmaf(c.w + c.z + rt  + up.w + dn.w + fm.w + fp.w, kw, bi), 0.f);
    if (store)
        *(uint2*)(dst + base_c + (size_t)dd * PL + (size_t)(h0 + ty) * DW + w0) =
            f4_to_h4(v);
    return (v.x + v.y) + (v.z + v.w);
}

// ---------------------------------------------------------------------------
// Kernel 2 (x2): ONE fused erosion pair (fresh launch, L1-cached loads).
// block (32,8)=256 thr; grid (1, 16 hb, 4 db * 8 bc) = 512 blocks; 1 wave.
// ---------------------------------------------------------------------------
__global__ void __launch_bounds__(256, 4)
erode2_kernel(const __half* __restrict__ src,
              __half*       __restrict__ dst,
              const unsigned char* __restrict__ srcFlag,
              unsigned char*       __restrict__ dstFlag,
              const float* __restrict__ weight,
              const float* __restrict__ kern,
              const float* __restrict__ bias,
              float c1, float c2, int store)
{
    const int tx  = threadIdx.x;
    const int ty  = threadIdx.y;
    const int tid = ty * 32 + tx;
    const int hb  = blockIdx.y;          // 0..15
    const int db  = blockIdx.z & 3;      // 0..3
    const int bc  = blockIdx.z >> 2;     // 0..7

    const int h0   = hb * 8;
    const int d0   = db * 32;
    const int ht0  = hb * 2;
    const int dtg0 = d0 >> 2;
    const size_t base_c = (size_t)bc * V;

    __shared__ unsigned char s_f[4][10];
    __shared__ unsigned char s_act[8];
    __shared__ unsigned char s_dstf[8][2];
    __shared__ unsigned char s_skip;

    if (tid < 40) {
        int fh = tid & 3, fg = tid >> 2;
        int ht = ht0 - 1 + fh;
        int g  = dtg0 - 1 + fg;
        unsigned char v = 0;
        if ((unsigned)ht < 32u && (unsigned)g < 32u)
            v = srcFlag[bc * 1024 + g * 32 + ht];
        s_f[fh][fg] = v;
    }
    if (tid >= 64 && tid < 80) {
        int k = tid - 64, sg = k >> 1, hh = k & 1;
        s_dstf[sg][hh] = store ? dstFlag[bc * 1024 + (dtg0 + sg) * 32 + ht0 + hh] : 0;
    }
    __syncthreads();
    if (tid < 8) {
        unsigned a = 0;
        #pragma unroll
        for (int dh = 0; dh < 4; ++dh)
            #pragma unroll
            for (int dg = 0; dg < 3; ++dg)
                a |= s_f[dh][tid + dg];
        s_act[tid] = a ? 1 : 0;
    }
    __syncthreads();
    if (tid == 0) {
        unsigned any = 0;
        #pragma unroll
        for (int s = 0; s < 8; ++s)
            any |= (unsigned)s_act[s] | s_dstf[s][0] | s_dstf[s][1];
        s_skip = any ? 0 : 1;
    }
    __syncthreads();
    if (s_skip) return;

    const float kw = __ldg(&kern[13]);
    const float bi = __ldg(&bias[bc & 3]);

    __shared__ __align__(16) float s_src[4][12][128];
    __shared__ __align__(16) float s_mid[4][10][128];
    __shared__ float s_w[8];

    float acc_mid   = 0.f;
    float block_out = 0.f;
    bool  have = false;

    #pragma unroll 1
    for (int seg = 0; seg < 8; ++seg) {
        const int ds  = d0 + seg * 4;
        const int dtg = dtg0 + seg;

        if (!s_act[seg]) {
            if (store && s_dstf[seg][ty >> 2]) {
                uint2 z; z.x = 0u; z.y = 0u;
                #pragma unroll
                for (int j = 0; j < 4; ++j)
                    *(uint2*)(dst + base_c + (size_t)(ds + j) * PL +
                              (size_t)(h0 + ty) * DW + tx * 4) = z;
                if (tx == 0 && (ty & 3) == 0)
                    dstFlag[bc * 1024 + dtg * 32 + ht0 + (ty >> 2)] = 0;
            }
            have = false;
            continue;
        }

        if (!have) {
            load_src_plane(s_src, src, base_c, ds - 2, h0, tid);
            load_src_plane(s_src, src, base_c, ds - 1, h0, tid);
            load_src_plane(s_src, src, base_c, ds,     h0, tid);
            load_src_plane(s_src, src, base_c, ds + 1, h0, tid);
            __syncthreads();
            acc_mid += mid_row(s_src, s_mid, ds - 1, ty, h0, tx, kw, bi, d0, d0 + 31);
            if (ty < 2)
                acc_mid += mid_row(s_src, s_mid, ds - 1, ty + 8, h0, tx, kw, bi, d0, d0 + 31);
            acc_mid += mid_row(s_src, s_mid, ds, ty, h0, tx, kw, bi, d0, d0 + 31);
            if (ty < 2)
                acc_mid += mid_row(s_src, s_mid, ds, ty + 8, h0, tx, kw, bi, d0, d0 + 31);
            __syncthreads();
            have = true;
        }

        float segsum = 0.f;
        #pragma unroll
        for (int j = 0; j < 4; j += 2) {
            const int dd = ds + j;
            load_src_plane(s_src, src, base_c, dd + 2, h0, tid);
            load_src_plane(s_src, src, base_c, dd + 3, h0, tid);
            __syncthreads();
            acc_mid += mid_row(s_src, s_mid, dd + 1, ty, h0, tx, kw, bi, d0, d0 + 31);
            if (ty < 2)
                acc_mid += mid_row(s_src, s_mid, dd + 1, ty + 8, h0, tx, kw, bi, d0, d0 + 31);
            acc_mid += mid_row(s_src, s_mid, dd + 2, ty, h0, tx, kw, bi, d0, d0 + 31);
            if (ty < 2)
                acc_mid += mid_row(s_src, s_mid, dd + 2, ty + 8, h0, tx, kw, bi, d0, d0 + 31);
            __syncthreads();
            segsum += out_plane(s_mid, dst, base_c, dd,     h0, tx, ty, kw, bi, store);
            segsum += out_plane(s_mid, dst, base_c, dd + 1, h0, tx, ty, kw, bi, store);
        }

        float r = segsum;
        #pragma unroll
        for (int off = 16; off > 0; off >>= 1)
            r += __shfl_down_sync(0xffffffffu, r, off);
        if (tx == 0) s_w[ty] = r;
        __syncthreads();
        if (tid == 0) {
            float t0 = (s_w[0] + s_w[1]) + (s_w[2] + s_w[3]);
            float t1 = (s_w[4] + s_w[5]) + (s_w[6] + s_w[7]);
            if (store) {
                dstFlag[bc * 1024 + dtg * 32 + ht0]     = (t0 > 0.f) ? 1 : 0;
                dstFlag[bc * 1024 + dtg * 32 + ht0 + 1] = (t1 > 0.f) ? 1 : 0;
            }
            block_out += t0 + t1;
        }
        __syncthreads();
    }

    float r = acc_mid;
    #pragma unroll
    for (int off = 16; off > 0; off >>= 1)
        r += __shfl_down_sync(0xffffffffu, r, off);
    if (tx == 0) s_w[ty] = r;
    __syncthreads();
    if (tid == 0) {
        float midsum = ((s_w[0] + s_w[1]) + (s_w[2] + s_w[3])) +
                       ((s_w[4] + s_w[5]) + (s_w[6] + s_w[7]));
        double total = (double)c1 * (double)midsum + (double)c2 * (double)block_out;
        if (total != 0.0)
            atomicAdd(&g_acc, total * (double)__ldg(&weight[bc]));
    }
}

// ---------------------------------------------------------------------------
// Software grid barrier (all NBLK blocks co-resident; monotonic counter).
// ---------------------------------------------------------------------------
__device__ __forceinline__ void grid_barrier(int tid, unsigned target)
{
    __syncthreads();
    if (tid == 0) {
        __threadfence();
        atomicAdd(&g_bar, 1u);
        while (*(volatile unsigned int*)&g_bar < target)
            __nanosleep(64);
        __threadfence();
    }
    __syncthreads();
}

// ---------------------------------------------------------------------------
// Kernel 3 (x1, persistent): erosion pairs p=2,3,4 (steps 5..10) — the mostly
// dead tail — with grid barriers between phases; L2-only loads (stale-L1 safe).
// Finalizes the mean via completion counter.
// ---------------------------------------------------------------------------
__global__ void __launch_bounds__(256, 4)
erode_tail_kernel(const float* __restrict__ weight,
                  const float* __restrict__ kern,
                  const float* __restrict__ bias,
                  float* __restrict__ outp)
{
    const int tx  = threadIdx.x;
    const int ty  = threadIdx.y;
    const int tid = ty * 32 + tx;
    const int hb  = blockIdx.y;
    const int db  = blockIdx.z & 3;
    const int bc  = blockIdx.z >> 2;

    const int h0   = hb * 8;
    const int d0   = db * 32;
    const int ht0  = hb * 2;
    const int dtg0 = d0 >> 2;
    const size_t base_c = (size_t)bc * V;

    const float kw  = __ldg(&kern[13]);
    const float bi  = __ldg(&bias[bc & 3]);
    const float wgt = __ldg(&weight[bc]);

    __shared__ unsigned char s_f[4][10];
    __shared__ unsigned char s_act[8];
    __shared__ unsigned char s_dstf[8][2];
    __shared__ unsigned char s_skip;
    __shared__ __align__(16) float s_src[4][12][128];
    __shared__ __align__(16) float s_mid[4][10][128];
    __shared__ float s_w[8];

    #pragma unroll 1
    for (int p = 2; p < 5; ++p) {
        const __half* src = (p & 1) ? g_bufB : g_bufA;
        __half*       dst = (p & 1) ? g_bufA : g_bufB;
        const unsigned char* srcFlag = (p & 1) ? g_flagB : g_flagA;
        unsigned char*       dstFlag = (p & 1) ? g_flagA : g_flagB;
        const float c1 = (float)((2 * p + 1) * (2 * p + 1));
        const float c2 = (float)((2 * p + 2) * (2 * p + 2));
        const int store = (p < 4) ? 1 : 0;

        if (tid < 40) {
            int fh = tid & 3, fg = tid >> 2;
            int ht = ht0 - 1 + fh;
            int g  = dtg0 - 1 + fg;
            unsigned char v = 0;
            if ((unsigned)ht < 32u && (unsigned)g < 32u)
                v = __ldcg(&srcFlag[bc * 1024 + g * 32 + ht]);
            s_f[fh][fg] = v;
        }
        if (tid >= 64 && tid < 80) {
            int k = tid - 64, sg = k >> 1, hh = k & 1;
            s_dstf[sg][hh] = store ? __ldcg(&dstFlag[bc * 1024 + (dtg0 + sg) * 32 + ht0 + hh]) : 0;
        }
        __syncthreads();
        if (tid < 8) {
            unsigned a = 0;
            #pragma unroll
            for (int dh = 0; dh < 4; ++dh)
                #pragma unroll
                for (int dg = 0; dg < 3; ++dg)
                    a |= s_f[dh][tid + dg];
            s_act[tid] = a ? 1 : 0;
        }
        __syncthreads();
        if (tid == 0) {
            unsigned any = 0;
            #pragma unroll
            for (int s = 0; s < 8; ++s)
                any |= (unsigned)s_act[s] | s_dstf[s][0] | s_dstf[s][1];
            s_skip = any ? 0 : 1;
        }
        __syncthreads();

        if (!s_skip) {
            float acc_mid   = 0.f;
            float block_out = 0.f;
            bool  have = false;

            #pragma unroll 1
            for (int seg = 0; seg < 8; ++seg) {
                const int ds  = d0 + seg * 4;
                const int dtg = dtg0 + seg;

                if (!s_act[seg]) {
                    if (store && s_dstf[seg][ty >> 2]) {
                        uint2 z; z.x = 0u; z.y = 0u;
                        #pragma unroll
                        for (int j = 0; j < 4; ++j)
                            *(uint2*)(dst + base_c + (size_t)(ds + j) * PL +
                                      (size_t)(h0 + ty) * DW + tx * 4) = z;
                        if (tx == 0 && (ty & 3) == 0)
                            dstFlag[bc * 1024 + dtg * 32 + ht0 + (ty >> 2)] = 0;
                    }
                    have = false;
                    continue;
                }

                if (!have) {
                    load_src_plane_cg(s_src, src, base_c, ds - 2, h0, tid);
                    load_src_plane_cg(s_src, src, base_c, ds - 1, h0, tid);
                    load_src_plane_cg(s_src, src, base_c, ds,     h0, tid);
                    load_src_plane_cg(s_src, src, base_c, ds + 1, h0, tid);
                    __syncthreads();
                    acc_mid += mid_row(s_src, s_mid, ds - 1, ty, h0, tx, kw, bi, d0, d0 + 31);
                    if (ty < 2)
                        acc_mid += mid_row(s_src, s_mid, ds - 1, ty + 8, h0, tx, kw, bi, d0, d0 + 31);
                    acc_mid += mid_row(s_src, s_mid, ds, ty, h0, tx, kw, bi, d0, d0 + 31);
                    if (ty < 2)
                        acc_mid += mid_row(s_src, s_mid, ds, ty + 8, h0, tx, kw, bi, d0, d0 + 31);
                    __syncthreads();
                    have = true;
                }

                float segsum = 0.f;
                #pragma unroll
                for (int j = 0; j < 4; j += 2) {
                    const int dd = ds + j;
                    load_src_plane_cg(s_src, src, base_c, dd + 2, h0, tid);
                    load_src_plane_cg(s_src, src, base_c, dd + 3, h0, tid);
                    __syncthreads();
                    acc_mid += mid_row(s_src, s_mid, dd + 1, ty, h0, tx, kw, bi, d0, d0 + 31);
                    if (ty < 2)
                        acc_mid += mid_row(s_src, s_mid, dd + 1, ty + 8, h0, tx, kw, bi, d0, d0 + 31);
                    acc_mid += mid_row(s_src, s_mid, dd + 2, ty, h0, tx, kw, bi, d0, d0 + 31);
                    if (ty < 2)
                        acc_mid += mid_row(s_src, s_mid, dd + 2, ty + 8, h0, tx, kw, bi, d0, d0 + 31);
                    __syncthreads();
                    segsum += out_plane(s_mid, dst, base_c, dd,     h0, tx, ty, kw, bi, store);
                    segsum += out_plane(s_mid, dst, base_c, dd + 1, h0, tx, ty, kw, bi, store);
                }

                float r = segsum;
                #pragma unroll
                for (int off = 16; off > 0; off >>= 1)
                    r += __shfl_down_sync(0xffffffffu, r, off);
                if (tx == 0) s_w[ty] = r;
                __syncthreads();
                if (tid == 0) {
                    float t0 = (s_w[0] + s_w[1]) + (s_w[2] + s_w[3]);
                    float t1 = (s_w[4] + s_w[5]) + (s_w[6] + s_w[7]);
                    if (store) {
                        dstFlag[bc * 1024 + dtg * 32 + ht0]     = (t0 > 0.f) ? 1 : 0;
                        dstFlag[bc * 1024 + dtg * 32 + ht0 + 1] = (t1 > 0.f) ? 1 : 0;
                    }
                    block_out += t0 + t1;
                }
                __syncthreads();
            }

            float r = acc_mid;
            #pragma unroll
            for (int off = 16; off > 0; off >>= 1)
                r += __shfl_down_sync(0xffffffffu, r, off);
            if (tx == 0) s_w[ty] = r;
            __syncthreads();
            if (tid == 0) {
                float midsum = ((s_w[0] + s_w[1]) + (s_w[2] + s_w[3])) +
                               ((s_w[4] + s_w[5]) + (s_w[6] + s_w[7]));
                double total = (double)c1 * (double)midsum + (double)c2 * (double)block_out;
                if (total != 0.0)
                    atomicAdd(&g_acc, total * (double)wgt);
            }
        }

        if (p < 4)
            grid_barrier(tid, (unsigned)(NBLK * (p - 1)));   // targets NBLK, 2*NBLK
    }

    // ---- finalize: last finished block writes the mean and resets state ----
    if (tid == 0) {
        __threadfence();
        unsigned old = atomicAdd(&g_cnt, 1u);
        if (old == NBLK - 1) {
            volatile double* pacc = &g_acc;
            double acc = *pacc;
            outp[0] = (float)(acc / (double)NTOT);
            *pacc = 0.0;                       // restore invariants for next replay
            *(volatile unsigned int*)&g_bar = 0u;
            __threadfence();
            g_cnt = 0;
        }
    }
}

// ---------------------------------------------------------------------------
extern "C" void kernel_launch(void* const* d_in, const int* in_sizes, int n_in,
                              void* d_out, int out_size)
{
    const float* inp    = (const float*)d_in[0];
    const int*   tgt    = (const int*)  d_in[1];
    const float* weight = (const float*)d_in[2];
    const float* kern   = (const float*)d_in[3];
    const float* bias   = (const float*)d_in[4];
    float* out = (float*)d_out;

    __half* bufA; cudaGetSymbolAddress((void**)&bufA, g_bufA);
    __half* bufB; cudaGetSymbolAddress((void**)&bufB, g_bufB);
    unsigned char* flagA; cudaGetSymbolAddress((void**)&flagA, g_flagA);
    unsigned char* flagB; cudaGetSymbolAddress((void**)&flagB, g_flagB);

    init_op_kernel<<<(NB_SPATIAL / 4 + 255) / 256, 256>>>(inp, tgt, bufA);

    dim3 blk(32, 8, 1);
    dim3 grd(1, 16, 4 * NBC);

    // pass 0 (steps 1,2): A -> B ; pass 1 (steps 3,4): B -> A  (L1-cached)
    erode2_kernel<<<grd, blk>>>(bufA, bufB, flagA, flagB, weight, kern, bias,
                                1.0f, 4.0f, 1);
    erode2_kernel<<<grd, blk>>>(bufB, bufA, flagB, flagA, weight, kern, bias,
                                9.0f, 16.0f, 1);

    // passes 2..4 (steps 5..10): persistent tail + fused finalize
    erode_tail_kernel<<<grd, blk>>>(weight, kern, bias, out);
}

// round 16
// speedup vs baseline: 1.0521x; 1.0487x over previous
#include <cuda_runtime.h>
#include <cuda_fp16.h>

// Problem geometry
#define DW   128
#define PL   (128*128)
#define V    (128*128*128)
#define NBC  8
#define NTOT (NBC*V)
#define NB_SPATIAL (2*V)
#define NTILES (NBC*32*32)        // flags: bc x dtg(32) x ht(32); tile = 128w x 4h x 4d
#define SLOT4(p) (((p) + 8) & 3)  // ring-of-4 slot, valid for p >= -8
#define NBLK 512                  // erode grid size

// Static device scratch (allowed). op fields stored as fp16 (values in [0,1]).
__device__ __half        g_bufA[NTOT];
__device__ __half        g_bufB[NTOT];
__device__ unsigned char g_flagA[NTILES];
__device__ unsigned char g_flagB[NTILES];
__device__ double        g_acc;     // zero-init; reset by finalizer
__device__ unsigned int  g_cnt;     // zero-init; reset by finalizer

// ---- fp16 <-> fp32 quad helpers -------------------------------------------
__device__ __forceinline__ uint2 f4_to_h4(float4 v)
{
    __half2 lo = __float22half2_rn(make_float2(v.x, v.y));
    __half2 hi = __float22half2_rn(make_float2(v.z, v.w));
    uint2 r;
    r.x = *(unsigned int*)&lo;
    r.y = *(unsigned int*)&hi;
    return r;
}
__device__ __forceinline__ float4 h4_to_f4(unsigned int a, unsigned int b)
{
    float2 lo = __half22float2(*(__half2*)&a);
    float2 hi = __half22float2(*(__half2*)&b);
    return make_float4(lo.x, lo.y, hi.x, hi.y);
}

// ---------------------------------------------------------------------------
// Kernel 1: softmax over C + squared one-hot error -> bufA (op0, fp16).
// ---------------------------------------------------------------------------
__global__ void init_op_kernel(const float* __restrict__ inp,
                               const int*   __restrict__ tgt,
                               __half*      __restrict__ dst)
{
    int q = blockIdx.x * blockDim.x + threadIdx.x;      // quad index
    if (q == 0) g_acc = 0.0;
    if (q < NTILES) g_flagA[q] = 1;
    if (q >= NB_SPATIAL / 4) return;

    int idx = q * 4;
    int b = idx >> 21;
    int s = idx & (V - 1);

    const float* ip = inp + (size_t)b * 4 * V + s;
    float4 x0 = __ldcs((const float4*)(ip));
    float4 x1 = __ldcs((const float4*)(ip + V));
    float4 x2 = __ldcs((const float4*)(ip + 2 * V));
    float4 x3 = __ldcs((const float4*)(ip + 3 * V));
    int4   t4 = __ldcs((const int4*)(tgt + idx));

    float4 o0, o1, o2, o3;
    #pragma unroll
    for (int j = 0; j < 4; ++j) {
        float a0 = ((const float*)&x0)[j];
        float a1 = ((const float*)&x1)[j];
        float a2 = ((const float*)&x2)[j];
        float a3 = ((const float*)&x3)[j];
        int   t  = ((const int*)&t4)[j];

        float e0 = __expf(a0);
        float e1 = __expf(a1);
        float e2 = __expf(a2);
        float e3 = __expf(a3);
        float inv = 1.0f / (e0 + e1 + e2 + e3);

        float p0 = e0 * inv - (t == 0 ? 1.0f : 0.0f);
        float p1 = e1 * inv - (t == 1 ? 1.0f : 0.0f);
        float p2 = e2 * inv - (t == 2 ? 1.0f : 0.0f);
        float p3 = e3 * inv - (t == 3 ? 1.0f : 0.0f);

        ((float*)&o0)[j] = p0 * p0;
        ((float*)&o1)[j] = p1 * p1;
        ((float*)&o2)[j] = p2 * p2;
        ((float*)&o3)[j] = p3 * p3;
    }

    __half* op = dst + (size_t)b * 4 * V + s;
    *(uint2*)(op)         = f4_to_h4(o0);
    *(uint2*)(op + V)     = f4_to_h4(o1);
    *(uint2*)(op + 2 * V) = f4_to_h4(o2);
    *(uint2*)(op + 3 * V) = f4_to_h4(o3);
}

// ---------------------------------------------------------------------------
// Fused-pair erosion helpers (ring-of-4 fp32 smem buffers, fp16 global)
// ---------------------------------------------------------------------------
__device__ __forceinline__ void load_src_plane(
    float (*ssrc)[12][128], const __half* __restrict__ src,
    size_t base_c, int p, int h0, int tid)
{
    const int slot = SLOT4(p);
    if (tid < 192) {
        int r = tid >> 4, cu = tid & 15;
        int h = h0 - 2 + r;
        float4 a = make_float4(0.f, 0.f, 0.f, 0.f);
        float4 b = a;
        if ((unsigned)p < 128u && (unsigned)h < 128u) {
            uint4 u = *(const uint4*)(src + base_c + (size_t)p * PL +
                                      (size_t)h * DW + cu * 8);
            a = h4_to_f4(u.x, u.y);
            b = h4_to_f4(u.z, u.w);
        }
        *(float4*)&ssrc[slot][r][cu * 8]     = a;
        *(float4*)&ssrc[slot][r][cu * 8 + 4] = b;
    }
}

__device__ __forceinline__ float mid_row(
    float (*ssrc)[12][128], float (*smid)[10][128],
    int m, int rr, int h0, int tx, float kw, float bi, int dlo, int dhi)
{
    const int w0 = tx * 4;
    const int h  = h0 - 1 + rr;
    float4 v = make_float4(0.f, 0.f, 0.f, 0.f);
    if ((unsigned)m < 128u && (unsigned)h < 128u) {
        const int r  = rr + 1;                  // src row for this h
        const int s0 = SLOT4(m);
        float4 c  = *(float4*)&ssrc[s0][r][w0];
        float4 up = *(float4*)&ssrc[s0][r - 1][w0];
        float4 dn = *(float4*)&ssrc[s0][r + 1][w0];
        float4 fm = *(float4*)&ssrc[SLOT4(m - 1)][r][w0];
        float4 fp = *(float4*)&ssrc[SLOT4(m + 1)][r][w0];
        float lf = (tx == 0)  ? 0.f : ssrc[s0][r][w0 - 1];
        float rt = (tx == 31) ? 0.f : ssrc[s0][r][w0 + 4];
        v.x = fmaxf(fmaf(c.x + lf  + c.y + up.x + dn.x + fm.x + fp.x, kw, bi), 0.f);
        v.y = fmaxf(fmaf(c.y + c.x + c.z + up.y + dn.y + fm.y + fp.y, kw, bi), 0.f);
        v.z = fmaxf(fmaf(c.z + c.y + c.w + up.z + dn.z + fm.z + fp.z, kw, bi), 0.f);
        v.w = fmaxf(fmaf(c.w + c.z + rt  + up.w + dn.w + fm.w + fp.w, kw, bi), 0.f);
    }
    *(float4*)&smid[SLOT4(m)][rr][w0] = v;
    if (m >= dlo && m <= dhi && rr >= 1 && rr <= 8)
        return (v.x + v.y) + (v.z + v.w);
    return 0.f;
}

__device__ __forceinline__ float out_plane(
    float (*smid)[10][128], __half* __restrict__ dst, size_t base_c,
    int dd, int h0, int tx, int ty, float kw, float bi, int store)
{
    const int w0 = tx * 4;
    const int rr = ty + 1;
    const int s0 = SLOT4(dd);
    float4 c  = *(float4*)&smid[s0][rr][w0];
    float4 up = *(float4*)&smid[s0][rr - 1][w0];
    float4 dn = *(float4*)&smid[s0][rr + 1][w0];
    float4 fm = *(float4*)&smid[SLOT4(dd - 1)][rr][w0];
    float4 fp = *(float4*)&smid[SLOT4(dd + 1)][rr][w0];
    float lf = (tx == 0)  ? 0.f : smid[s0][rr][w0 - 1];
    float rt = (tx == 31) ? 0.f : smid[s0][rr][w0 + 4];
    float4 v;
    v.x = fmaxf(fmaf(c.x + lf  + c.y + up.x + dn.x + fm.x + fp.x, kw, bi), 0.f);
    v.y = fmaxf(fmaf(c.y + c.x + c.z + up.y + dn.y + fm.y + fp.y, kw, bi), 0.f);
    v.z = fmaxf(fmaf(c.z + c.y + c.w + up.z + dn.z + fm.z + fp.z, kw, bi), 0.f);
    v.w = fmaxf(fmaf(c.w + c.z + rt  + up.w + dn.w + fm.w + fp.w, kw, bi), 0.f);
    if (store)
        *(uint2*)(dst + base_c + (size_t)dd * PL + (size_t)(h0 + ty) * DW + w0) =
            f4_to_h4(v);
    return (v.x + v.y) + (v.z + v.w);
}

// ---------------------------------------------------------------------------
// Kernel 2 (x5): TWO fused erosion steps, 2 d-planes per barrier period,
// tile sparsity with whole-block skip. Launched with PDL: grid-dependency
// sync at entry before any flag/field read. Pass 4 also finalizes the mean.
// block (32,8)=256 thr; grid (1, 16 hb, 4 db * 8 bc) = 512 blocks; 1 wave.
// ---------------------------------------------------------------------------
__global__ void __launch_bounds__(256, 4)
erode2_kernel(const __half* __restrict__ src,
              __half*       __restrict__ dst,
              const unsigned char* __restrict__ srcFlag,
              unsigned char*       __restrict__ dstFlag,
              const float* __restrict__ weight,
              const float* __restrict__ kern,
              const float* __restrict__ bias,
              float c1, float c2, int store, int last,
              float* __restrict__ outp)
{
    const int tx  = threadIdx.x;
    const int ty  = threadIdx.y;
    const int tid = ty * 32 + tx;
    const int hb  = blockIdx.y;          // 0..15
    const int db  = blockIdx.z & 3;      // 0..3
    const int bc  = blockIdx.z >> 2;     // 0..7

    const int h0   = hb * 8;
    const int d0   = db * 32;
    const int ht0  = hb * 2;
    const int dtg0 = d0 >> 2;
    const size_t base_c = (size_t)bc * V;

    // Constants are graph inputs (written before the graph) — safe pre-sync.
    const float kw = __ldg(&kern[13]);
    const float bi = __ldg(&bias[bc & 3]);

#if __CUDA_ARCH__ >= 900
    // PDL: wait for the predecessor kernel's memory before reading flags/fields.
    cudaGridDependencySynchronize();
#endif

    __shared__ unsigned char s_f[4][10];     // src flags: ht0-1..+2  x  dtg0-1..+8
    __shared__ unsigned char s_act[8];       // per-segment activity
    __shared__ unsigned char s_dstf[8][2];   // dst flags per segment / ht tile
    __shared__ unsigned char s_skip;

    // --- cooperative flag gather (one pass per block) ---
    if (tid < 40) {
        int fh = tid & 3, fg = tid >> 2;     // 4 x 10
        int ht = ht0 - 1 + fh;
        int g  = dtg0 - 1 + fg;
        unsigned char v = 0;
        if ((unsigned)ht < 32u && (unsigned)g < 32u)
            v = srcFlag[bc * 1024 + g * 32 + ht];
        s_f[fh][fg] = v;
    }
    if (tid >= 64 && tid < 80) {
        int k = tid - 64, sg = k >> 1, hh = k & 1;
        s_dstf[sg][hh] = store ? dstFlag[bc * 1024 + (dtg0 + sg) * 32 + ht0 + hh] : 0;
    }
    __syncthreads();
    if (tid < 8) {
        unsigned a = 0;
        #pragma unroll
        for (int dh = 0; dh < 4; ++dh)
            #pragma unroll
            for (int dg = 0; dg < 3; ++dg)
                a |= s_f[dh][tid + dg];
        s_act[tid] = a ? 1 : 0;
    }
    __syncthreads();
    if (tid == 0) {
        unsigned any = 0;
        #pragma unroll
        for (int s = 0; s < 8; ++s)
            any |= (unsigned)s_act[s] | s_dstf[s][0] | s_dstf[s][1];
        s_skip = any ? 0 : 1;
    }
    __syncthreads();

    if (!s_skip) {
        __shared__ __align__(16) float s_src[4][12][128];
        __shared__ __align__(16) float s_mid[4][10][128];
        __shared__ float s_w[8];

        float acc_mid   = 0.f;   // per-thread, whole block
        float block_out = 0.f;   // only meaningful in thread 0
        bool  have = false;

        #pragma unroll 1
        for (int seg = 0; seg < 8; ++seg) {
            const int ds  = d0 + seg * 4;
            const int dtg = dtg0 + seg;

            if (!s_act[seg]) {
                // dead neighborhood -> output tile must be zero
                if (store && s_dstf[seg][ty >> 2]) {
                    uint2 z; z.x = 0u; z.y = 0u;
                    #pragma unroll
                    for (int j = 0; j < 4; ++j)
                        *(uint2*)(dst + base_c + (size_t)(ds + j) * PL +
                                  (size_t)(h0 + ty) * DW + tx * 4) = z;
                    if (tx == 0 && (ty & 3) == 0)
                        dstFlag[bc * 1024 + dtg * 32 + ht0 + (ty >> 2)] = 0;
                }
                have = false;
                continue;
            }

            if (!have) {
                // prologue: fill src ring (4 planes), then mids ds-1, ds
                load_src_plane(s_src, src, base_c, ds - 2, h0, tid);
                load_src_plane(s_src, src, base_c, ds - 1, h0, tid);
                load_src_plane(s_src, src, base_c, ds,     h0, tid);
                load_src_plane(s_src, src, base_c, ds + 1, h0, tid);
                __syncthreads();
                acc_mid += mid_row(s_src, s_mid, ds - 1, ty, h0, tx, kw, bi, d0, d0 + 31);
                if (ty < 2)
                    acc_mid += mid_row(s_src, s_mid, ds - 1, ty + 8, h0, tx, kw, bi, d0, d0 + 31);
                acc_mid += mid_row(s_src, s_mid, ds, ty, h0, tx, kw, bi, d0, d0 + 31);
                if (ty < 2)
                    acc_mid += mid_row(s_src, s_mid, ds, ty + 8, h0, tx, kw, bi, d0, d0 + 31);
                __syncthreads();
                have = true;
            }

            float segsum = 0.f;
            #pragma unroll
            for (int j = 0; j < 4; j += 2) {
                const int dd = ds + j;
                load_src_plane(s_src, src, base_c, dd + 2, h0, tid);
                load_src_plane(s_src, src, base_c, dd + 3, h0, tid);
                __syncthreads();
                acc_mid += mid_row(s_src, s_mid, dd + 1, ty, h0, tx, kw, bi, d0, d0 + 31);
                if (ty < 2)
                    acc_mid += mid_row(s_src, s_mid, dd + 1, ty + 8, h0, tx, kw, bi, d0, d0 + 31);
                acc_mid += mid_row(s_src, s_mid, dd + 2, ty, h0, tx, kw, bi, d0, d0 + 31);
                if (ty < 2)
                    acc_mid += mid_row(s_src, s_mid, dd + 2, ty + 8, h0, tx, kw, bi, d0, d0 + 31);
                __syncthreads();
                segsum += out_plane(s_mid, dst, base_c, dd,     h0, tx, ty, kw, bi, store);
                segsum += out_plane(s_mid, dst, base_c, dd + 1, h0, tx, ty, kw, bi, store);
            }

            // per-segment reduction -> flags + running out-sum
            float r = segsum;
            #pragma unroll
            for (int off = 16; off > 0; off >>= 1)
                r += __shfl_down_sync(0xffffffffu, r, off);
            if (tx == 0) s_w[ty] = r;
            __syncthreads();
            if (tid == 0) {
                float t0 = (s_w[0] + s_w[1]) + (s_w[2] + s_w[3]);
                float t1 = (s_w[4] + s_w[5]) + (s_w[6] + s_w[7]);
                if (store) {
                    dstFlag[bc * 1024 + dtg * 32 + ht0]     = (t0 > 0.f) ? 1 : 0;
                    dstFlag[bc * 1024 + dtg * 32 + ht0 + 1] = (t1 > 0.f) ? 1 : 0;
                }
                block_out += t0 + t1;
            }
            __syncthreads();
        }

        // final block reduction of mid-sum + single atomic
        float r = acc_mid;
        #pragma unroll
        for (int off = 16; off > 0; off >>= 1)
            r += __shfl_down_sync(0xffffffffu, r, off);
        if (tx == 0) s_w[ty] = r;
        __syncthreads();
        if (tid == 0) {
            float midsum = ((s_w[0] + s_w[1]) + (s_w[2] + s_w[3])) +
                           ((s_w[4] + s_w[5]) + (s_w[6] + s_w[7]));
            double total = (double)c1 * (double)midsum + (double)c2 * (double)block_out;
            if (total != 0.0)
                atomicAdd(&g_acc, total * (double)__ldg(&weight[bc]));
        }
    }

    // ---- final pass: last finished block writes the mean and resets state ----
    if (last && tid == 0) {
        __threadfence();
        unsigned old = atomicAdd(&g_cnt, 1u);
        if (old == NBLK - 1) {
            volatile double* pacc = &g_acc;
            double acc = *pacc;
            outp[0] = (float)(acc / (double)NTOT);
            *pacc = 0.0;                 // restore invariant for next replay
            __threadfence();
            g_cnt = 0;
        }
    }
}

// ---------------------------------------------------------------------------
extern "C" void kernel_launch(void* const* d_in, const int* in_sizes, int n_in,
                              void* d_out, int out_size)
{
    const float* inp    = (const float*)d_in[0];
    const int*   tgt    = (const int*)  d_in[1];
    const float* weight = (const float*)d_in[2];
    const float* kern   = (const float*)d_in[3];
    const float* bias   = (const float*)d_in[4];
    float* out = (float*)d_out;

    __half* bufA; cudaGetSymbolAddress((void**)&bufA, g_bufA);
    __half* bufB; cudaGetSymbolAddress((void**)&bufB, g_bufB);
    unsigned char* flagA; cudaGetSymbolAddress((void**)&flagA, g_flagA);
    unsigned char* flagB; cudaGetSymbolAddress((void**)&flagB, g_flagB);

    init_op_kernel<<<(NB_SPATIAL / 4 + 255) / 256, 256>>>(inp, tgt, bufA);

    dim3 blk(32, 8, 1);
    dim3 grd(1, 16, 4 * NBC);

    cudaLaunchAttribute attrs[1];
    attrs[0].id = cudaLaunchAttributeProgrammaticStreamSerialization;
    attrs[0].val.programmaticStreamSerializationAllowed = 1;

    cudaLaunchConfig_t cfg = {};
    cfg.gridDim  = grd;
    cfg.blockDim = blk;
    cfg.dynamicSmemBytes = 0;
    cfg.stream = 0;
    cfg.attrs = attrs;
    cfg.numAttrs = 1;

    __half* src = bufA;         unsigned char* sf = flagA;
    __half* dst = bufB;         unsigned char* df = flagB;
    for (int p = 0; p < 5; ++p) {
        float c1 = (float)((2 * p + 1) * (2 * p + 1));
        float c2 = (float)((2 * p + 2) * (2 * p + 2));
        int store = (p < 4) ? 1 : 0;
        int last  = (p == 4) ? 1 : 0;
        cudaLaunchKernelEx(&cfg, erode2_kernel,
                           (const __half*)src, dst,
                           (const unsigned char*)sf, df,
                           weight, kern, bias, c1, c2, store, last, out);
        __half* t = src; src = dst; dst = t;
        unsigned char* tf = sf; sf = df; df = tf;
    }
}